// round 13
// baseline (speedup 1.0000x reference)
#include <cuda_runtime.h>
#include <math.h>

// ---- DCT basis as compile-time immediates (truncated-pi basis, <4e-7 err) --
#define P0 0.35355339059327373f
#define P1 0.4903926402016152f
#define P2 0.46193976625564337f
#define P3 0.4157348061512726f
#define P4 0.3535533905932738f
#define P5 0.2777851165098011f
#define P6 0.1913417161825449f
#define P7 0.09754516100806412f

// dst = C * src, butterfly form (even rows symmetric, odd rows antisymmetric)
#define MUL_ROWS(dst, src) do { \
    float s0=(src)[0]+(src)[7], s1=(src)[1]+(src)[6], s2=(src)[2]+(src)[5], s3=(src)[3]+(src)[4]; \
    float d0=(src)[0]-(src)[7], d1=(src)[1]-(src)[6], d2=(src)[2]-(src)[5], d3=(src)[3]-(src)[4]; \
    float ea=s0+s3, eb=s1+s2, ec=s0-s3, ed=s1-s2; \
    (dst)[0]=P0*(ea+eb); \
    (dst)[4]=P4*(ea-eb); \
    (dst)[2]=fmaf(P6,ed,P2*ec); \
    (dst)[6]=fmaf(-P2,ed,P6*ec); \
    (dst)[1]=fmaf(P7,d3,fmaf(P5,d2,fmaf(P3,d1,P1*d0))); \
    (dst)[3]=fmaf(-P5,d3,fmaf(-P1,d2,fmaf(-P7,d1,P3*d0))); \
    (dst)[5]=fmaf(P3,d3,fmaf(P7,d2,fmaf(-P1,d1,P5*d0))); \
    (dst)[7]=fmaf(-P1,d3,fmaf(P3,d2,fmaf(-P5,d1,P7*d0))); \
} while (0)

// dst = C^T * src, butterfly form (dst[i]=E_i+O_i, dst[7-i]=E_i-O_i)
#define MUL_COLS(dst, src) do { \
    float t0=P0*(src)[0], u4=P4*(src)[4]; \
    float ps=t0+u4, ms=t0-u4; \
    float E0=fmaf(P6,(src)[6],fmaf( P2,(src)[2],ps)); \
    float E1=fmaf(-P2,(src)[6],fmaf( P6,(src)[2],ms)); \
    float E2=fmaf( P2,(src)[6],fmaf(-P6,(src)[2],ms)); \
    float E3=fmaf(-P6,(src)[6],fmaf(-P2,(src)[2],ps)); \
    float O0=fmaf(P7,(src)[7],fmaf( P5,(src)[5],fmaf( P3,(src)[3],P1*(src)[1]))); \
    float O1=fmaf(-P5,(src)[7],fmaf(-P1,(src)[5],fmaf(-P7,(src)[3],P3*(src)[1]))); \
    float O2=fmaf( P3,(src)[7],fmaf( P7,(src)[5],fmaf(-P1,(src)[3],P5*(src)[1]))); \
    float O3=fmaf(-P1,(src)[7],fmaf( P3,(src)[5],fmaf(-P5,(src)[3],P7*(src)[1]))); \
    (dst)[0]=E0+O0; (dst)[7]=E0-O0; \
    (dst)[1]=E1+O1; (dst)[6]=E1-O1; \
    (dst)[2]=E2+O2; (dst)[5]=E2-O2; \
    (dst)[3]=E3+O3; (dst)[4]=E3-O3; \
} while (0)

// learned mask, COLUMN-major: g_Mc[c*8 + i] = M[i][c]
static __device__ float g_Mc[64];

__global__ void prep_kernel(const float* __restrict__ noise,
                            const float* __restrict__ qmat,
                            const float* __restrict__ qmw,
                            const float* __restrict__ w1, const float* __restrict__ b1,
                            const float* __restrict__ w2, const float* __restrict__ b2,
                            const float* __restrict__ w3, const float* __restrict__ b3)
{
    __shared__ float h1[16], h2[16], nr[18], coef[16];
    int t = threadIdx.x;  // 64 threads

    const float inv_sqrt2 = 0.7071067811865476f;
    if (t < 16) {
        float z = fmaf(noise[0], w1[t], b1[t]);
        h1[t] = 0.5f * z * (1.0f + erff(z * inv_sqrt2));
    }
    __syncthreads();
    if (t < 16) {
        float z = b2[t];
        #pragma unroll
        for (int k = 0; k < 16; k++) z = fmaf(h1[k], w2[k * 16 + t], z);
        h2[t] = 0.5f * z * (1.0f + erff(z * inv_sqrt2));
    }
    __syncthreads();
    if (t < 18) {
        float z = b3[t];
        #pragma unroll
        for (int k = 0; k < 16; k++) z = fmaf(h2[k], w3[k * 18 + t], z);
        nr[t] = z;
    }
    __syncthreads();
    if (t == 0) {
        float mx = qmw[0];
        #pragma unroll
        for (int i = 1; i < 16; i++) mx = fmaxf(mx, qmw[i]);
        float e[16], sum = 0.f;
        #pragma unroll
        for (int i = 0; i < 16; i++) { e[i] = expf(qmw[i] - mx); sum += e[i]; }
        float inv = 1.0f / sum;
        #pragma unroll
        for (int i = 0; i < 16; i++)
            coef[i] = (e[i] * inv * nr[0] + nr[1]) * nr[2 + i];
    }
    __syncthreads();

    if (t < 64) {
        int c = t >> 3, i = t & 7;          // write col-major
        float s = 0.f;
        #pragma unroll
        for (int q = 0; q < 16; q++) s = fmaf(coef[q], qmat[q * 64 + i * 8 + c], s);
        g_Mc[t] = s;
    }
}

// 2 lanes per 8x8 block. Lane parity p owns rows [4p,4p+4).
// Transposes via per-warp smem quadrant exchange; all 8-point transforms in
// butterfly form. low = C^T((C X C^T).*M)C ; high = X - low. x read once.
__global__ __launch_bounds__(256, 3) void dct_main(const float* __restrict__ x,
                                                   float* __restrict__ lo,
                                                   float* __restrict__ hi)
{
    __shared__ __align__(16) float Ms[64];         // col-major mask
    __shared__ float4 xb[8][4][32];                // 16 KB exchange buffer

    int tid  = threadIdx.x;
    int wid  = tid >> 5;
    int lane = tid & 31;
    if (tid < 64) Ms[tid] = g_Mc[tid];
    __syncthreads();

    int p   = tid & 1;                     // half-block owner
    int g   = blockIdx.x * 128 + (tid >> 1);   // global 8x8-block id
    int img = g >> 6;
    int blk = g & 63;
    int base = (img << 12) + ((blk >> 3) << 9) + ((blk & 7) << 3);
    int r0   = p << 2;                     // first owned row

    const float* xp = x + base + (r0 << 6);
    float X[32];
    #pragma unroll
    for (int i = 0; i < 4; i++) {
        float4 a = *reinterpret_cast<const float4*>(xp + (i << 6));
        float4 b = *reinterpret_cast<const float4*>(xp + (i << 6) + 4);
        X[i*8+0]=a.x; X[i*8+1]=a.y; X[i*8+2]=a.z; X[i*8+3]=a.w;
        X[i*8+4]=b.x; X[i*8+5]=b.y; X[i*8+6]=b.z; X[i*8+7]=b.w;
    }

    // S1: A rows = (X * C^T) rows r0+i  (row . C-rows = C*Xrow)
    float A[32];
    #pragma unroll
    for (int i = 0; i < 4; i++) MUL_ROWS(&A[i*8], &X[i*8]);

    // T1: quadrant exchange with peer lane (lane^1) via smem
    #pragma unroll
    for (int i = 0; i < 4; i++) {
        float4 s = p ? make_float4(A[i*8+0], A[i*8+1], A[i*8+2], A[i*8+3])
                     : make_float4(A[i*8+4], A[i*8+5], A[i*8+6], A[i*8+7]);
        xb[wid][i][lane] = s;
    }
    __syncwarp();
    #pragma unroll
    for (int i = 0; i < 4; i++) {
        float4 r = xb[wid][i][lane ^ 1];
        if (p) { A[i*8+0]=r.x; A[i*8+1]=r.y; A[i*8+2]=r.z; A[i*8+3]=r.w; }
        else   { A[i*8+4]=r.x; A[i*8+5]=r.y; A[i*8+6]=r.z; A[i*8+7]=r.w; }
    }
    __syncwarp();                          // buffer reuse below

    // S2+mask+S3 per owned column c = r0+j (in place in A)
    #pragma unroll
    for (int j = 0; j < 4; j++) {
        float v[8], w[8], z[8];
        #pragma unroll
        for (int i = 0; i < 4; i++) { v[i] = A[i*8+j]; v[4+i] = A[i*8+4+j]; }
        MUL_ROWS(w, v);                    // spectrum column
        const float4 m0 = *reinterpret_cast<const float4*>(&Ms[(r0+j) << 3]);
        const float4 m1 = *reinterpret_cast<const float4*>(&Ms[((r0+j) << 3) + 4]);
        w[0]*=m0.x; w[1]*=m0.y; w[2]*=m0.z; w[3]*=m0.w;
        w[4]*=m1.x; w[5]*=m1.y; w[6]*=m1.z; w[7]*=m1.w;
        MUL_COLS(z, w);                    // Z column
        #pragma unroll
        for (int i = 0; i < 4; i++) { A[i*8+j] = z[i]; A[i*8+4+j] = z[4+i]; }
    }

    // T2: identical quadrant exchange (same buffer)
    #pragma unroll
    for (int i = 0; i < 4; i++) {
        float4 s = p ? make_float4(A[i*8+0], A[i*8+1], A[i*8+2], A[i*8+3])
                     : make_float4(A[i*8+4], A[i*8+5], A[i*8+6], A[i*8+7]);
        xb[wid][i][lane] = s;
    }
    __syncwarp();
    #pragma unroll
    for (int i = 0; i < 4; i++) {
        float4 r = xb[wid][i][lane ^ 1];
        if (p) { A[i*8+0]=r.x; A[i*8+1]=r.y; A[i*8+2]=r.z; A[i*8+3]=r.w; }
        else   { A[i*8+4]=r.x; A[i*8+5]=r.y; A[i*8+6]=r.z; A[i*8+7]=r.w; }
    }

    // S4: low rows = Z*C ; high = X - low
    float* lp = lo + base + (r0 << 6);
    float* hp = hi + base + (r0 << 6);
    #pragma unroll
    for (int i = 0; i < 4; i++) {
        float l[8];
        MUL_COLS(l, &A[i*8]);
        *reinterpret_cast<float4*>(lp + (i << 6))     = make_float4(l[0], l[1], l[2], l[3]);
        *reinterpret_cast<float4*>(lp + (i << 6) + 4) = make_float4(l[4], l[5], l[6], l[7]);
        *reinterpret_cast<float4*>(hp + (i << 6)) =
            make_float4(X[i*8+0]-l[0], X[i*8+1]-l[1], X[i*8+2]-l[2], X[i*8+3]-l[3]);
        *reinterpret_cast<float4*>(hp + (i << 6) + 4) =
            make_float4(X[i*8+4]-l[4], X[i*8+5]-l[5], X[i*8+6]-l[6], X[i*8+7]-l[7]);
    }
}

extern "C" void kernel_launch(void* const* d_in, const int* in_sizes, int n_in,
                              void* d_out, int out_size)
{
    const float* x     = (const float*)d_in[0];
    const float* noise = (const float*)d_in[1];
    const float* qmat  = (const float*)d_in[2];
    const float* qmw   = (const float*)d_in[3];
    const float* w1    = (const float*)d_in[4];
    const float* b1    = (const float*)d_in[5];
    const float* w2    = (const float*)d_in[6];
    const float* b2    = (const float*)d_in[7];
    const float* w3    = (const float*)d_in[8];
    const float* b3    = (const float*)d_in[9];

    float* out = (float*)d_out;
    int N = out_size / 2;                 // elements per output tensor
    float* lo = out;
    float* hi = out + N;

    prep_kernel<<<1, 64>>>(noise, qmat, qmw, w1, b1, w2, b2, w3, b3);

    int nblocks8x8 = N / 64;              // 2 lanes per block -> 128 blocks/CTA
    dct_main<<<nblocks8x8 / 128, 256>>>(x, lo, hi);
}

// round 14
// speedup vs baseline: 1.0285x; 1.0285x over previous
#include <cuda_runtime.h>
#include <math.h>

// ---- DCT basis as compile-time immediates (truncated-pi basis, <4e-7 err) --
#define P0 0.35355339059327373f
#define P1 0.4903926402016152f
#define P2 0.46193976625564337f
#define P3 0.4157348061512726f
#define P4 0.3535533905932738f
#define P5 0.2777851165098011f
#define P6 0.1913417161825449f
#define P7 0.09754516100806412f

// dst = C * src, butterfly form (even rows symmetric, odd rows antisymmetric)
#define MUL_ROWS(dst, src) do { \
    float s0=(src)[0]+(src)[7], s1=(src)[1]+(src)[6], s2=(src)[2]+(src)[5], s3=(src)[3]+(src)[4]; \
    float d0=(src)[0]-(src)[7], d1=(src)[1]-(src)[6], d2=(src)[2]-(src)[5], d3=(src)[3]-(src)[4]; \
    float ea=s0+s3, eb=s1+s2, ec=s0-s3, ed=s1-s2; \
    (dst)[0]=P0*(ea+eb); \
    (dst)[4]=P4*(ea-eb); \
    (dst)[2]=fmaf(P6,ed,P2*ec); \
    (dst)[6]=fmaf(-P2,ed,P6*ec); \
    (dst)[1]=fmaf(P7,d3,fmaf(P5,d2,fmaf(P3,d1,P1*d0))); \
    (dst)[3]=fmaf(-P5,d3,fmaf(-P1,d2,fmaf(-P7,d1,P3*d0))); \
    (dst)[5]=fmaf(P3,d3,fmaf(P7,d2,fmaf(-P1,d1,P5*d0))); \
    (dst)[7]=fmaf(-P1,d3,fmaf(P3,d2,fmaf(-P5,d1,P7*d0))); \
} while (0)

// dst = C^T * src, butterfly form (dst[i]=E_i+O_i, dst[7-i]=E_i-O_i)
#define MUL_COLS(dst, src) do { \
    float t0=P0*(src)[0], u4=P4*(src)[4]; \
    float ps=t0+u4, ms=t0-u4; \
    float E0=fmaf(P6,(src)[6],fmaf( P2,(src)[2],ps)); \
    float E1=fmaf(-P2,(src)[6],fmaf( P6,(src)[2],ms)); \
    float E2=fmaf( P2,(src)[6],fmaf(-P6,(src)[2],ms)); \
    float E3=fmaf(-P6,(src)[6],fmaf(-P2,(src)[2],ps)); \
    float O0=fmaf(P7,(src)[7],fmaf( P5,(src)[5],fmaf( P3,(src)[3],P1*(src)[1]))); \
    float O1=fmaf(-P5,(src)[7],fmaf(-P1,(src)[5],fmaf(-P7,(src)[3],P3*(src)[1]))); \
    float O2=fmaf( P3,(src)[7],fmaf( P7,(src)[5],fmaf(-P1,(src)[3],P5*(src)[1]))); \
    float O3=fmaf(-P1,(src)[7],fmaf( P3,(src)[5],fmaf(-P5,(src)[3],P7*(src)[1]))); \
    (dst)[0]=E0+O0; (dst)[7]=E0-O0; \
    (dst)[1]=E1+O1; (dst)[6]=E1-O1; \
    (dst)[2]=E2+O2; (dst)[5]=E2-O2; \
    (dst)[3]=E3+O3; (dst)[4]=E3-O3; \
} while (0)

// learned mask, COLUMN-major: g_Mc[c*8 + i] = M[i][c]
static __device__ float g_Mc[64];

__global__ void prep_kernel(const float* __restrict__ noise,
                            const float* __restrict__ qmat,
                            const float* __restrict__ qmw,
                            const float* __restrict__ w1, const float* __restrict__ b1,
                            const float* __restrict__ w2, const float* __restrict__ b2,
                            const float* __restrict__ w3, const float* __restrict__ b3)
{
    __shared__ float h1[16], h2[16], nr[18], coef[16];
    int t = threadIdx.x;  // 64 threads

    const float inv_sqrt2 = 0.7071067811865476f;
    if (t < 16) {
        float z = fmaf(noise[0], w1[t], b1[t]);
        h1[t] = 0.5f * z * (1.0f + erff(z * inv_sqrt2));
    }
    __syncthreads();
    if (t < 16) {
        float z = b2[t];
        #pragma unroll
        for (int k = 0; k < 16; k++) z = fmaf(h1[k], w2[k * 16 + t], z);
        h2[t] = 0.5f * z * (1.0f + erff(z * inv_sqrt2));
    }
    __syncthreads();
    if (t < 18) {
        float z = b3[t];
        #pragma unroll
        for (int k = 0; k < 16; k++) z = fmaf(h2[k], w3[k * 18 + t], z);
        nr[t] = z;
    }
    __syncthreads();
    if (t == 0) {
        float mx = qmw[0];
        #pragma unroll
        for (int i = 1; i < 16; i++) mx = fmaxf(mx, qmw[i]);
        float e[16], sum = 0.f;
        #pragma unroll
        for (int i = 0; i < 16; i++) { e[i] = expf(qmw[i] - mx); sum += e[i]; }
        float inv = 1.0f / sum;
        #pragma unroll
        for (int i = 0; i < 16; i++)
            coef[i] = (e[i] * inv * nr[0] + nr[1]) * nr[2 + i];
    }
    __syncthreads();

    if (t < 64) {
        int c = t >> 3, i = t & 7;          // write col-major
        float s = 0.f;
        #pragma unroll
        for (int q = 0; q < 16; q++) s = fmaf(coef[q], qmat[q * 64 + i * 8 + c], s);
        g_Mc[t] = s;
    }
}

// 2 lanes per 8x8 block. Lane parity p owns rows [4p,4p+4).
// X is stashed in smem after S1 so only A[32] stays live in registers ->
// 64-reg cap -> 4 CTAs/SM. Transposes via per-warp smem quadrant exchange
// (two 2-row rounds through an 8 KB buffer). Butterfly transforms.
// low = C^T((C X C^T).*M)C ; high = X - low. x read once from DRAM.
__global__ __launch_bounds__(256, 4) void dct_main(const float* __restrict__ x,
                                                   float* __restrict__ lo,
                                                   float* __restrict__ hi)
{
    __shared__ __align__(16) float Ms[64];         // col-major mask (256 B)
    __shared__ float4 xb[8][2][32];                // 8 KB exchange buffer
    __shared__ float4 xs[8][256];                  // 32 KB X stash

    int tid  = threadIdx.x;
    int wid  = tid >> 5;
    int lane = tid & 31;
    if (tid < 64) Ms[tid] = g_Mc[tid];
    __syncthreads();

    int p   = tid & 1;                     // half-block owner
    int g   = blockIdx.x * 128 + (tid >> 1);   // global 8x8-block id
    int img = g >> 6;
    int blk = g & 63;
    int base = (img << 12) + ((blk >> 3) << 9) + ((blk & 7) << 3);
    int r0   = p << 2;                     // first owned row

    // Load X rows, run S1 row-by-row, stash X into smem, keep only A.
    const float* xp = x + base + (r0 << 6);
    float A[32];
    #pragma unroll
    for (int i = 0; i < 4; i++) {
        float4 a = *reinterpret_cast<const float4*>(xp + (i << 6));
        float4 b = *reinterpret_cast<const float4*>(xp + (i << 6) + 4);
        float r[8] = {a.x, a.y, a.z, a.w, b.x, b.y, b.z, b.w};
        MUL_ROWS(&A[i*8], r);              // S1: spectrum row r0+i (partial)
        xs[2*i][tid]   = a;                // stash X row for S4
        xs[2*i+1][tid] = b;
    }

    // T1: quadrant exchange with peer lane (lane^1), two rounds of 2 rows
    #pragma unroll
    for (int h = 0; h < 2; h++) {
        #pragma unroll
        for (int i2 = 0; i2 < 2; i2++) {
            int i = h*2 + i2;
            float4 s = p ? make_float4(A[i*8+0], A[i*8+1], A[i*8+2], A[i*8+3])
                         : make_float4(A[i*8+4], A[i*8+5], A[i*8+6], A[i*8+7]);
            xb[wid][i2][lane] = s;
        }
        __syncwarp();
        #pragma unroll
        for (int i2 = 0; i2 < 2; i2++) {
            int i = h*2 + i2;
            float4 r = xb[wid][i2][lane ^ 1];
            if (p) { A[i*8+0]=r.x; A[i*8+1]=r.y; A[i*8+2]=r.z; A[i*8+3]=r.w; }
            else   { A[i*8+4]=r.x; A[i*8+5]=r.y; A[i*8+6]=r.z; A[i*8+7]=r.w; }
        }
        __syncwarp();
    }

    // S2+mask+S3 per owned column c = r0+j (in place in A)
    #pragma unroll
    for (int j = 0; j < 4; j++) {
        float v[8], w[8], z[8];
        #pragma unroll
        for (int i = 0; i < 4; i++) { v[i] = A[i*8+j]; v[4+i] = A[i*8+4+j]; }
        MUL_ROWS(w, v);                    // spectrum column
        const float4 m0 = *reinterpret_cast<const float4*>(&Ms[(r0+j) << 3]);
        const float4 m1 = *reinterpret_cast<const float4*>(&Ms[((r0+j) << 3) + 4]);
        w[0]*=m0.x; w[1]*=m0.y; w[2]*=m0.z; w[3]*=m0.w;
        w[4]*=m1.x; w[5]*=m1.y; w[6]*=m1.z; w[7]*=m1.w;
        MUL_COLS(z, w);                    // Z column
        #pragma unroll
        for (int i = 0; i < 4; i++) { A[i*8+j] = z[i]; A[i*8+4+j] = z[4+i]; }
    }

    // T2: identical quadrant exchange
    #pragma unroll
    for (int h = 0; h < 2; h++) {
        #pragma unroll
        for (int i2 = 0; i2 < 2; i2++) {
            int i = h*2 + i2;
            float4 s = p ? make_float4(A[i*8+0], A[i*8+1], A[i*8+2], A[i*8+3])
                         : make_float4(A[i*8+4], A[i*8+5], A[i*8+6], A[i*8+7]);
            xb[wid][i2][lane] = s;
        }
        __syncwarp();
        #pragma unroll
        for (int i2 = 0; i2 < 2; i2++) {
            int i = h*2 + i2;
            float4 r = xb[wid][i2][lane ^ 1];
            if (p) { A[i*8+0]=r.x; A[i*8+1]=r.y; A[i*8+2]=r.z; A[i*8+3]=r.w; }
            else   { A[i*8+4]=r.x; A[i*8+5]=r.y; A[i*8+6]=r.z; A[i*8+7]=r.w; }
        }
        __syncwarp();
    }

    // S4: low rows = Z*C ; high = (X from smem) - low
    float* lp = lo + base + (r0 << 6);
    float* hp = hi + base + (r0 << 6);
    #pragma unroll
    for (int i = 0; i < 4; i++) {
        float l[8];
        MUL_COLS(l, &A[i*8]);
        float4 a = xs[2*i][tid];
        float4 b = xs[2*i+1][tid];
        *reinterpret_cast<float4*>(lp + (i << 6))     = make_float4(l[0], l[1], l[2], l[3]);
        *reinterpret_cast<float4*>(lp + (i << 6) + 4) = make_float4(l[4], l[5], l[6], l[7]);
        *reinterpret_cast<float4*>(hp + (i << 6)) =
            make_float4(a.x - l[0], a.y - l[1], a.z - l[2], a.w - l[3]);
        *reinterpret_cast<float4*>(hp + (i << 6) + 4) =
            make_float4(b.x - l[4], b.y - l[5], b.z - l[6], b.w - l[7]);
    }
}

extern "C" void kernel_launch(void* const* d_in, const int* in_sizes, int n_in,
                              void* d_out, int out_size)
{
    const float* x     = (const float*)d_in[0];
    const float* noise = (const float*)d_in[1];
    const float* qmat  = (const float*)d_in[2];
    const float* qmw   = (const float*)d_in[3];
    const float* w1    = (const float*)d_in[4];
    const float* b1    = (const float*)d_in[5];
    const float* w2    = (const float*)d_in[6];
    const float* b2    = (const float*)d_in[7];
    const float* w3    = (const float*)d_in[8];
    const float* b3    = (const float*)d_in[9];

    float* out = (float*)d_out;
    int N = out_size / 2;                 // elements per output tensor
    float* lo = out;
    float* hi = out + N;

    prep_kernel<<<1, 64>>>(noise, qmat, qmw, w1, b1, w2, b2, w3, b3);

    int nblocks8x8 = N / 64;              // 2 lanes per block -> 128 blocks/CTA
    dct_main<<<nblocks8x8 / 128, 256>>>(x, lo, hi);
}